// round 16
// baseline (speedup 1.0000x reference)
#include <cuda_runtime.h>
#include <cuda_fp16.h>
#include <math.h>
#include <stdint.h>

#define BSZ   2048
#define DIMV  200
#define NENT  100000
#define NTS   400
#define EPSV  1e-5f
#define REG_OFF 204800000L
#define T_OFF   204800005L
#define KP    24            // A smem row pitch in halves (48B)
#define EP    216           // E smem row pitch in halves (432B)
#define NEPAD 100096        // 782*128
#define KDPAD 208           // E fp16 row pitch (200 padded to 208)
#define KWROWS 256          // W-transpose row allocation
#define KBIG  40000         // inner K of hgemm
#define HZ    50            // hgemm K-split
#define HSPAN (2500 / HZ)
#define WROWS 80            // W smem rows per tile (72 used for wide tile)
#define PRED_SMEM (128*EP*2 + 3*128*KP*2)   // 55296 + 18432 = 73728 bytes

// ---------------- device-global scratch ----------------
__device__ __align__(16) float g_lhsT[DIMV * BSZ];    // lhs transposed [d][b]
__device__ __align__(16) float g_reltT[DIMV * BSZ];   // rel*time [k][b]
__device__ __align__(16) float g_lhsnT[DIMV * BSZ];   // bn0(lhs) [d][b]
__device__ __align__(16) float g_hT[DIMV * BSZ];      // h transposed [e][b]
__device__ float g_acc[8];
__device__ int   g_idx64;
__device__ __align__(16) __half gEh[(long)NEPAD * KDPAD];  // E fp16 padded
__device__ __align__(16) __half gWTh[(long)KWROWS * KBIG]; // [e][K]
__device__ __align__(16) __half gAh[BSZ * DIMV];           // h_n fp16 [b][200]

// ---------------- helpers ----------------
__device__ __forceinline__ void ldsm_x4(uint32_t& r0, uint32_t& r1, uint32_t& r2, uint32_t& r3,
                                        uint32_t addr) {
    asm volatile("ldmatrix.sync.aligned.m8n8.x4.shared.b16 {%0,%1,%2,%3}, [%4];"
                 : "=r"(r0), "=r"(r1), "=r"(r2), "=r"(r3) : "r"(addr));
}
__device__ __forceinline__ void mma_f16(float& c0, float& c1, float& c2, float& c3,
                                        uint32_t a0, uint32_t a1, uint32_t a2, uint32_t a3,
                                        uint32_t b0, uint32_t b1) {
    asm volatile("mma.sync.aligned.m16n8k16.row.col.f32.f16.f16.f32 "
                 "{%0,%1,%2,%3},{%4,%5,%6,%7},{%8,%9},{%0,%1,%2,%3};"
                 : "+f"(c0), "+f"(c1), "+f"(c2), "+f"(c3)
                 : "r"(a0), "r"(a1), "r"(a2), "r"(a3), "r"(b0), "r"(b1));
}
__device__ __forceinline__ void mma_f16_k8(float& c0, float& c1, float& c2, float& c3,
                                           uint32_t a0, uint32_t a1, uint32_t b0) {
    asm volatile("mma.sync.aligned.m16n8k8.row.col.f32.f16.f16.f32 "
                 "{%0,%1,%2,%3},{%4,%5},{%6},{%0,%1,%2,%3};"
                 : "+f"(c0), "+f"(c1), "+f"(c2), "+f"(c3)
                 : "r"(a0), "r"(a1), "r"(b0));
}
#define CPA16(dst_u32, src_ptr) \
    asm volatile("cp.async.cg.shared.global [%0], [%1], 16;" :: "r"(dst_u32), "l"(src_ptr))
#define CP_COMMIT() asm volatile("cp.async.commit_group;")
#define CP_WAIT1()  asm volatile("cp.async.wait_group 1;")
#define CP_WAIT0()  asm volatile("cp.async.wait_group 0;")

// ---------------- K0a: small init (g_acc, g_idx64) ----------------
__global__ void k_init(const int* __restrict__ xraw) {
    int i = threadIdx.x;
    if (i < 8) g_acc[i] = 0.f;
    if (i == 0) {
        int odd = xraw[1] | xraw[3] | xraw[5] | xraw[7] |
                  xraw[9] | xraw[11] | xraw[13] | xraw[15];
        g_idx64 = (odd == 0) ? 1 : 0;
    }
}

// ---------------- K0b: zero g_hT (side stream, before hgemm) ----------------
__global__ void k_zero() {
    int i = blockIdx.x * blockDim.x + threadIdx.x;
    int stride = gridDim.x * blockDim.x;
    for (int j = i; j < BSZ * DIMV; j += stride) g_hT[j] = 0.f;
}

// ---------------- E -> fp16, padded (side stream) ----------------
__global__ void k_ehalf(const float* __restrict__ E) {
    long idx = (long)blockIdx.x * blockDim.x + threadIdx.x;
    if (idx >= (long)NEPAD * 26) return;
    int row = (int)(idx / 26);
    int c8  = (int)(idx % 26) * 8;
    long o  = (long)row * KDPAD + c8;
    if (row < NENT && c8 < DIMV) {
        const float* p = E + (long)row * DIMV + c8;
        #pragma unroll
        for (int j = 0; j < 8; j++) gEh[o + j] = __float2half(p[j]);
    } else {
        #pragma unroll
        for (int j = 0; j < 8; j++) gEh[o + j] = __float2half(0.f);
    }
}

// ---------------- transpose W -> gWTh[e][K] fp16, single pass, fused norm4(W) ----------------
__global__ void k_whalf(const float* __restrict__ W) {
    __shared__ float sT[32][33];
    __shared__ float sr[8];
    int K0 = blockIdx.x * 32;     // 1250 blocks
    int tx = threadIdx.x & 31, ty = threadIdx.x >> 5;
    float p4 = 0.f;
    for (int e0 = 0; e0 < DIMV; e0 += 32) {
        __syncthreads();
        #pragma unroll
        for (int r = 0; r < 4; r++) {
            int Kr = K0 + ty + 8 * r;
            int e  = e0 + tx;
            float v = (e < DIMV) ? W[(long)Kr * DIMV + e] : 0.f;
            sT[ty + 8 * r][tx] = v;
            float a = v * v; p4 += a * a;
        }
        __syncthreads();
        #pragma unroll
        for (int r = 0; r < 4; r++) {
            int ew = e0 + ty + 8 * r;
            if (ew < DIMV)
                gWTh[(long)ew * KBIG + K0 + tx] = __float2half(sT[tx][ty + 8 * r]);
        }
    }
    #pragma unroll
    for (int o = 16; o > 0; o >>= 1) p4 += __shfl_down_sync(0xffffffffu, p4, o);
    if (tx == 0) sr[ty] = p4;
    __syncthreads();
    if (threadIdx.x == 0) {
        float s = 0.f;
        for (int i = 0; i < 8; i++) s += sr[i];
        atomicAdd(&g_acc[4], s);
    }
}

// ---------------- K1: gather (transposed writes) + reg norms 1..3 ----------------
__global__ void k_gather(const int* __restrict__ x32,
                         const float* __restrict__ E,
                         const float* __restrict__ R,
                         const float* __restrict__ RnoT,
                         const float* __restrict__ T) {
    __shared__ int sidx[4];
    __shared__ float sr[3][8];
    int b = blockIdx.x, t = threadIdx.x;
    if (t < 4) {
        int v;
        if (g_idx64) { const long long* x64 = (const long long*)x32; v = (int)x64[(long)b * 4 + t]; }
        else         { v = x32[b * 4 + t]; }
        sidx[t] = v;
    }
    __syncthreads();
    int x0 = sidx[0], x1 = sidx[1], x2 = sidx[2], x3 = sidx[3];
    float p1 = 0.f, p2 = 0.f, p3 = 0.f;
    if (t < DIMV) {
        float lv = E[(long)x0 * DIMV + t];
        float rv = R[x1 * DIMV + t];
        float tv = T[x3 * DIMV + t];
        float rt = rv * tv;
        g_lhsT[t * BSZ + b]  = lv;
        g_reltT[t * BSZ + b] = rt;
        float rn = RnoT[x1 * DIMV + t];
        float rh = E[(long)x2 * DIMV + t];
        float a = rt * rt;  p1 = a * a;
        float c = rn * rn;  p2 = c * c;
        float e2 = rh * rh; p3 = e2 * e2;
    }
    #pragma unroll
    for (int o = 16; o > 0; o >>= 1) {
        p1 += __shfl_down_sync(0xffffffffu, p1, o);
        p2 += __shfl_down_sync(0xffffffffu, p2, o);
        p3 += __shfl_down_sync(0xffffffffu, p3, o);
    }
    int lane = t & 31, w = t >> 5;
    if (lane == 0) { sr[0][w] = p1; sr[1][w] = p2; sr[2][w] = p3; }
    __syncthreads();
    if (t == 0) {
        float s1 = 0.f, s2 = 0.f, s3 = 0.f;
        for (int i = 0; i < 8; i++) { s1 += sr[0][i]; s2 += sr[1][i]; s3 += sr[2][i]; }
        atomicAdd(&g_acc[1], s1);
        atomicAdd(&g_acc[2], s2);
        atomicAdd(&g_acc[3], s3);
    }
}

// ---------------- K2: fused BN0 + norm4(lhs_n) ----------------
__global__ __launch_bounds__(256) void k_bn0(const float* __restrict__ gamma,
                                             const float* __restrict__ beta) {
    __shared__ float s1[8], s2[8], sSS[2];
    int d = blockIdx.x, t = threadIdx.x;
    float4 v0 = *(const float4*)&g_lhsT[d * BSZ + t * 8];
    float4 v1 = *(const float4*)&g_lhsT[d * BSZ + t * 8 + 4];
    float vs[8] = {v0.x, v0.y, v0.z, v0.w, v1.x, v1.y, v1.z, v1.w};
    float sum = 0.f, sq = 0.f;
    #pragma unroll
    for (int j = 0; j < 8; j++) { sum += vs[j]; sq += vs[j] * vs[j]; }
    #pragma unroll
    for (int o = 16; o > 0; o >>= 1) {
        sum += __shfl_down_sync(0xffffffffu, sum, o);
        sq  += __shfl_down_sync(0xffffffffu, sq, o);
    }
    int lane = t & 31, w = t >> 5;
    if (lane == 0) { s1[w] = sum; s2[w] = sq; }
    __syncthreads();
    if (t == 0) {
        float S = 0.f, Q = 0.f;
        for (int i = 0; i < 8; i++) { S += s1[i]; Q += s2[i]; }
        float mean = S * (1.f / BSZ);
        float var  = Q * (1.f / BSZ) - mean * mean;
        float inv  = rsqrtf(var + EPSV);
        float sc   = gamma[d] * inv;
        sSS[0] = sc;
        sSS[1] = beta[d] - mean * sc;
    }
    __syncthreads();
    float sc = sSS[0], sh = sSS[1];
    float p4 = 0.f;
    #pragma unroll
    for (int j = 0; j < 8; j++) {
        float nv = vs[j] * sc + sh;
        vs[j] = nv;
        float a = nv * nv; p4 += a * a;
    }
    *(float4*)&g_lhsnT[d * BSZ + t * 8]     = make_float4(vs[0], vs[1], vs[2], vs[3]);
    *(float4*)&g_lhsnT[d * BSZ + t * 8 + 4] = make_float4(vs[4], vs[5], vs[6], vs[7]);
    #pragma unroll
    for (int o = 16; o > 0; o >>= 1) p4 += __shfl_down_sync(0xffffffffu, p4, o);
    if (lane == 0) s1[w] = p4;
    __syncthreads();
    if (t == 0) {
        float s = 0.f;
        for (int i = 0; i < 8; i++) s += s1[i];
        atomicAdd(&g_acc[0], s);
    }
}

// ---------------- K4: h GEMM, fp16 MMA; grid.y=3, wide last tile (N=72) ----------------
__global__ __launch_bounds__(256) void k_hgemm() {
    __shared__ __align__(16) __half sAh[2][128 * KP];
    __shared__ __align__(16) __half sWh[2][WROWS * KP];
    const int t    = threadIdx.x;
    const int lane = t & 31;
    const int w    = t >> 5;
    const int wm   = (w & 1) * 64;
    const int wn   = (w >> 1) * 16;
    const int b0   = blockIdx.x * 128;
    const int e0   = blockIdx.y * 64;
    const int cbeg = blockIdx.z * HSPAN;
    const int nN   = (e0 == 128 && wn == 48) ? 3 : 2;

    const uint32_t uAh = (uint32_t)__cvta_generic_to_shared(sAh);
    const uint32_t uWh = (uint32_t)__cvta_generic_to_shared(sWh);
    const uint32_t bufA = 128 * KP * 2;
    const uint32_t bufW = WROWS * KP * 2;

    const int kk = t & 15;
    const int m4 = t >> 4;

    auto stageW = [&](int buf, int kc) {
        if (t < 2 * WROWS) {
            const __half* src = gWTh + (long)(e0 + (t >> 1)) * KBIG + kc + (t & 1) * 8;
            uint32_t dst = uWh + buf * bufW + (uint32_t)(((t >> 1)) * KP + (t & 1) * 8) * 2;
            CPA16(dst, src);
        }
    };
    auto stageA = [&](int buf, int kc) {
        int K = kc + kk;
        int k = K / DIMV;
        int d = K - k * DIMV;
        const float* rp = &g_reltT[k * BSZ + b0 + m4 * 8];
        const float* lp = &g_lhsnT[d * BSZ + b0 + m4 * 8];
        #pragma unroll
        for (int g = 0; g < 2; g++) {
            float4 rv = *(const float4*)(rp + g * 4);
            float4 lv = *(const float4*)(lp + g * 4);
            float pr[4] = {rv.x * lv.x, rv.y * lv.y, rv.z * lv.z, rv.w * lv.w};
            #pragma unroll
            for (int j = 0; j < 4; j++)
                sAh[buf][(m4 * 8 + g * 4 + j) * KP + kk] = __float2half(pr[j]);
        }
    };

    float c[4][3][4];
    #pragma unroll
    for (int mi = 0; mi < 4; mi++)
        #pragma unroll
        for (int ni = 0; ni < 3; ni++)
            #pragma unroll
            for (int q = 0; q < 4; q++) c[mi][ni][q] = 0.f;

    stageW(0, cbeg * 16);
    CP_COMMIT();
    stageA(0, cbeg * 16);

    for (int cI = 0; cI < HSPAN; cI++) {
        int buf = cI & 1;
        if (cI + 1 < HSPAN) {
            stageW(buf ^ 1, (cbeg + cI + 1) * 16);
            CP_COMMIT();
            stageA(buf ^ 1, (cbeg + cI + 1) * 16);
        } else {
            CP_COMMIT();
        }
        CP_WAIT1();
        __syncthreads();

        uint32_t aAh = uAh + buf * bufA;
        uint32_t aWh = uWh + buf * bufW;
        uint32_t ah[4][4];
        {
            int arow = wm + (lane & 15);
            int acol = (lane >> 4) * 8;
            #pragma unroll
            for (int mi = 0; mi < 4; mi++) {
                uint32_t off = (uint32_t)(((arow + mi * 16) * KP + acol) * 2);
                ldsm_x4(ah[mi][0], ah[mi][1], ah[mi][2], ah[mi][3], aAh + off);
            }
        }
        uint32_t bh[4], bx[4];
        {
            int r = lane & 7, seg = lane >> 3;
            int brow = wn + ((seg & 2) ? 8 : 0) + r;
            int bcol = (seg & 1) * 8;
            uint32_t off = (uint32_t)((brow * KP + bcol) * 2);
            ldsm_x4(bh[0], bh[1], bh[2], bh[3], aWh + off);
            if (nN == 3) {
                uint32_t off2 = (uint32_t)(((brow + 16) * KP + bcol) * 2);
                ldsm_x4(bx[0], bx[1], bx[2], bx[3], aWh + off2);
            }
        }
        #pragma unroll
        for (int mi = 0; mi < 4; mi++) {
            float* c0 = c[mi][0];
            mma_f16(c0[0], c0[1], c0[2], c0[3],
                    ah[mi][0], ah[mi][1], ah[mi][2], ah[mi][3], bh[0], bh[1]);
            float* c1 = c[mi][1];
            mma_f16(c1[0], c1[1], c1[2], c1[3],
                    ah[mi][0], ah[mi][1], ah[mi][2], ah[mi][3], bh[2], bh[3]);
            if (nN == 3) {
                float* c2 = c[mi][2];
                mma_f16(c2[0], c2[1], c2[2], c2[3],
                        ah[mi][0], ah[mi][1], ah[mi][2], ah[mi][3], bx[0], bx[1]);
            }
        }
        __syncthreads();
    }

    #pragma unroll
    for (int mi = 0; mi < 4; mi++) {
        for (int ni = 0; ni < nN; ni++) {
            int r  = b0 + wm + mi * 16 + (lane >> 2);
            int cg = e0 + wn + ni * 8 + (lane & 3) * 2;
            if (cg < DIMV) {
                float* cc = c[mi][ni];
                atomicAdd(&g_hT[cg * BSZ + r], cc[0]);
                atomicAdd(&g_hT[(cg + 1) * BSZ + r], cc[1]);
                atomicAdd(&g_hT[cg * BSZ + r + 8], cc[2]);
                atomicAdd(&g_hT[(cg + 1) * BSZ + r + 8], cc[3]);
            }
        }
    }
}

// ---------------- K5: fused BN1 -> gAh fp16 [b][200] ----------------
__global__ __launch_bounds__(256) void k_bn1(const float* __restrict__ gamma,
                                             const float* __restrict__ beta) {
    __shared__ float s1[8], s2[8], sSS[2];
    int e = blockIdx.x, t = threadIdx.x;
    float4 v0 = *(const float4*)&g_hT[e * BSZ + t * 8];
    float4 v1 = *(const float4*)&g_hT[e * BSZ + t * 8 + 4];
    float vs[8] = {v0.x, v0.y, v0.z, v0.w, v1.x, v1.y, v1.z, v1.w};
    float sum = 0.f, sq = 0.f;
    #pragma unroll
    for (int j = 0; j < 8; j++) { sum += vs[j]; sq += vs[j] * vs[j]; }
    #pragma unroll
    for (int o = 16; o > 0; o >>= 1) {
        sum += __shfl_down_sync(0xffffffffu, sum, o);
        sq  += __shfl_down_sync(0xffffffffu, sq, o);
    }
    int lane = t & 31, w = t >> 5;
    if (lane == 0) { s1[w] = sum; s2[w] = sq; }
    __syncthreads();
    if (t == 0) {
        float S = 0.f, Q = 0.f;
        for (int i = 0; i < 8; i++) { S += s1[i]; Q += s2[i]; }
        float mean = S * (1.f / BSZ);
        float var  = Q * (1.f / BSZ) - mean * mean;
        float inv  = rsqrtf(var + EPSV);
        float sc   = gamma[e] * inv;
        sSS[0] = sc;
        sSS[1] = beta[e] - mean * sc;
    }
    __syncthreads();
    float sc = sSS[0], sh = sSS[1];
    #pragma unroll
    for (int j = 0; j < 8; j++)
        gAh[(t * 8 + j) * DIMV + e] = __float2half(vs[j] * sc + sh);
}

// ---------------- K7: pred = h_n @ E^T; 3-buffer A ring, 1 sync/iter ----------------
__global__ __launch_bounds__(256) void k_pred(float* __restrict__ out) {
    extern __shared__ __align__(16) char dynsmem[];
    __half* sE = (__half*)dynsmem;                       // 128 x EP
    __half* sA = (__half*)(dynsmem + 128 * EP * 2);      // 3 x 128 x KP
    const int t    = threadIdx.x;
    const int lane = t & 31;
    const int w    = t >> 5;
    const int wm   = (w & 1) * 64;
    const int wn   = (w >> 1) * 32;
    const int et   = blockIdx.x / 3;
    const int grp  = blockIdx.x - et * 3;
    const int e0   = et * 128;
    const int mbeg = (grp == 0) ? 0 : (grp == 1 ? 6 : 11);
    const int mend = (grp == 0) ? 6 : (grp == 1 ? 11 : 16);
    const int nit  = (mend - mbeg) * 13;

    const uint32_t uE = (uint32_t)__cvta_generic_to_shared(sE);
    const uint32_t uA = (uint32_t)__cvta_generic_to_shared(sA);
    const uint32_t bufA = 128 * KP * 2;

    const int srow = t >> 1;
    const int sch  = (t & 1) * 8;
    auto stageA = [&](int buf, int mIdx, int kcIdx) {
        if (kcIdx < 12 || (t & 1) == 0)
            CPA16(uA + buf * bufA + (uint32_t)(srow * KP + sch) * 2,
                  gAh + (long)(mIdx * 128 + srow) * DIMV + kcIdx * 16 + sch);
    };

    // group 0: E tile + A chunk for it=0
    for (int i = t; i < 128 * 26; i += 256) {
        int row = i / 26, c = i - row * 26;
        CPA16(uE + (uint32_t)(row * EP + c * 8) * 2,
              gEh + (long)(e0 + row) * KDPAD + c * 8);
    }
    stageA(0, mbeg, 0);
    CP_COMMIT();
    // group 1: A chunk for it=1
    stageA(1, mbeg, 1);
    CP_COMMIT();

    float c[4][4][4];
    #pragma unroll
    for (int mi = 0; mi < 4; mi++)
        #pragma unroll
        for (int ni = 0; ni < 4; ni++)
            #pragma unroll
            for (int q = 0; q < 4; q++) c[mi][ni][q] = 0.f;

    int m = mbeg, kc = 0;
    for (int it = 0; it < nit; it++) {
        CP_WAIT1();
        __syncthreads();

        if (it + 2 < nit) {
            int k2 = kc + 2, m2 = m;
            if (k2 >= 13) { k2 -= 13; m2++; }
            stageA((it + 2) % 3, m2, k2);
        }
        CP_COMMIT();

        uint32_t aA = uA + (it % 3) * bufA;
        uint32_t ah[4][4];
        {
            int arow = wm + (lane & 15);
            int acol = (lane >> 4) * 8;
            #pragma unroll
            for (int mi = 0; mi < 4; mi++) {
                uint32_t off = (uint32_t)(((arow + mi * 16) * KP + acol) * 2);
                ldsm_x4(ah[mi][0], ah[mi][1], ah[mi][2], ah[mi][3], aA + off);
            }
        }
        uint32_t bh[2][4];
        {
            int r = lane & 7, seg = lane >> 3;
            int brow_in = ((seg & 2) ? 8 : 0) + r;
            int bcol = (seg & 1) * 8;
            #pragma unroll
            for (int p = 0; p < 2; p++) {
                uint32_t off = (uint32_t)(((wn + p * 16 + brow_in) * EP + kc * 16 + bcol) * 2);
                ldsm_x4(bh[p][0], bh[p][1], bh[p][2], bh[p][3], uE + off);
            }
        }
        if (kc < 12) {
            #pragma unroll
            for (int mi = 0; mi < 4; mi++) {
                #pragma unroll
                for (int ni = 0; ni < 4; ni++) {
                    int p = ni >> 1, q = (ni & 1) * 2;
                    float* cc = c[mi][ni];
                    mma_f16(cc[0], cc[1], cc[2], cc[3],
                            ah[mi][0], ah[mi][1], ah[mi][2], ah[mi][3], bh[p][q], bh[p][q + 1]);
                }
            }
        } else {
            #pragma unroll
            for (int mi = 0; mi < 4; mi++) {
                #pragma unroll
                for (int ni = 0; ni < 4; ni++) {
                    int p = ni >> 1, q = (ni & 1) * 2;
                    float* cc = c[mi][ni];
                    mma_f16_k8(cc[0], cc[1], cc[2], cc[3],
                               ah[mi][0], ah[mi][1], bh[p][q]);
                }
            }
        }

        if (kc == 12) {
            #pragma unroll
            for (int mi = 0; mi < 4; mi++) {
                #pragma unroll
                for (int ni = 0; ni < 4; ni++) {
                    int r  = m * 128 + wm + mi * 16 + (lane >> 2);
                    int cg = e0 + wn + ni * 8 + (lane & 3) * 2;
                    float* cc = c[mi][ni];
                    if (cg < NENT) {
                        *(float2*)&out[(long)r * NENT + cg]       = make_float2(cc[0], cc[1]);
                        *(float2*)&out[(long)(r + 8) * NENT + cg] = make_float2(cc[2], cc[3]);
                    }
                    cc[0] = cc[1] = cc[2] = cc[3] = 0.f;
                }
            }
            kc = 0; m++;
        } else {
            kc++;
        }
    }
}

// ---------------- K9: reg outputs + T passthrough (side stream) ----------------
__global__ void k_tail(const float* __restrict__ T, float* __restrict__ out) {
    int i = blockIdx.x * blockDim.x + threadIdx.x;
    if (i < 5) out[REG_OFF + i] = powf(g_acc[i], 0.25f);
    if (i < NTS * DIMV) out[T_OFF + i] = T[i];
}

// ---------------- launch ----------------
extern "C" void kernel_launch(void* const* d_in, const int* in_sizes, int n_in,
                              void* d_out, int out_size) {
    const int*   x    = (const int*)d_in[0];
    const float* E    = (const float*)d_in[1];
    const float* R    = (const float*)d_in[2];
    const float* RnoT = (const float*)d_in[3];
    const float* T    = (const float*)d_in[4];
    const float* W    = (const float*)d_in[5];
    const float* g0   = (const float*)d_in[6];
    const float* be0  = (const float*)d_in[7];
    const float* g1   = (const float*)d_in[8];
    const float* be1  = (const float*)d_in[9];
    float* out = (float*)d_out;

    static cudaStream_t s2 = 0;
    static cudaEvent_t evF = 0, evW = 0, evE = 0, evB = 0, evT = 0;
    if (s2 == 0) {
        cudaStreamCreateWithFlags(&s2, cudaStreamNonBlocking);
        cudaEventCreateWithFlags(&evF, cudaEventDisableTiming);
        cudaEventCreateWithFlags(&evW, cudaEventDisableTiming);
        cudaEventCreateWithFlags(&evE, cudaEventDisableTiming);
        cudaEventCreateWithFlags(&evB, cudaEventDisableTiming);
        cudaEventCreateWithFlags(&evT, cudaEventDisableTiming);
    }
    cudaFuncSetAttribute(k_pred, cudaFuncAttributeMaxDynamicSharedMemorySize, PRED_SMEM);

    k_init<<<1, 256>>>(x);
    cudaEventRecord(evF, 0);
    cudaStreamWaitEvent(s2, evF, 0);
    k_zero<<<512, 256, 0, s2>>>();
    k_whalf<<<1250, 256, 0, s2>>>(W);
    cudaEventRecord(evW, s2);
    k_ehalf<<<(int)(((long)NEPAD * 26 + 255) / 256), 256, 0, s2>>>(E);
    cudaEventRecord(evE, s2);

    k_gather<<<BSZ, 256>>>(x, E, R, RnoT, T);
    k_bn0<<<DIMV, 256>>>(g0, be0);
    cudaEventRecord(evB, 0);
    cudaStreamWaitEvent(0, evW, 0);
    k_hgemm<<<dim3(16, 3, HZ), 256>>>();
    k_bn1<<<DIMV, 256>>>(g1, be1);

    cudaStreamWaitEvent(s2, evB, 0);
    k_tail<<<320, 256, 0, s2>>>(T, out);
    cudaEventRecord(evT, s2);

    cudaStreamWaitEvent(0, evE, 0);
    k_pred<<<2346, 256, PRED_SMEM>>>(out);
    cudaStreamWaitEvent(0, evT, 0);
}

// round 17
// speedup vs baseline: 1.0091x; 1.0091x over previous
#include <cuda_runtime.h>
#include <cuda_fp16.h>
#include <math.h>
#include <stdint.h>

#define BSZ   2048
#define DIMV  200
#define NENT  100000
#define NTS   400
#define EPSV  1e-5f
#define REG_OFF 204800000L
#define T_OFF   204800005L
#define KP    24            // A smem row pitch in halves (48B)
#define EP    216           // E smem row pitch in halves (432B)
#define NEPAD 100096        // 782*128
#define KDPAD 208           // E fp16 row pitch (200 padded to 208)
#define KWROWS 256          // W-transpose row allocation
#define KBIG  40000         // inner K of hgemm
#define HZ    25            // hgemm K-split (measured best)
#define HSPAN (2500 / HZ)
#define WROWS 80            // W smem rows per tile (72 used for wide tile)
#define PRED_SMEM (128*EP*2 + 3*128*KP*2)   // 73728 bytes

// ---------------- device-global scratch ----------------
__device__ __align__(16) float g_lhsT[DIMV * BSZ];    // lhs transposed [d][b]
__device__ __align__(16) float g_reltT[DIMV * BSZ];   // rel*time [k][b]
__device__ __align__(16) float g_lhsnT[DIMV * BSZ];   // bn0(lhs) [d][b]
__device__ __align__(16) float g_hT[DIMV * BSZ];      // h transposed [e][b]
__device__ float g_acc[8];
__device__ int   g_idx64;
__device__ __align__(16) __half gEh[(long)NEPAD * KDPAD];  // E fp16 padded
__device__ __align__(16) __half gWTh[(long)KWROWS * KBIG]; // [e][K]
__device__ __align__(16) __half gAh[BSZ * DIMV];           // h_n fp16 [b][200]

// ---------------- helpers ----------------
__device__ __forceinline__ void ldsm_x4(uint32_t& r0, uint32_t& r1, uint32_t& r2, uint32_t& r3,
                                        uint32_t addr) {
    asm volatile("ldmatrix.sync.aligned.m8n8.x4.shared.b16 {%0,%1,%2,%3}, [%4];"
                 : "=r"(r0), "=r"(r1), "=r"(r2), "=r"(r3) : "r"(addr));
}
__device__ __forceinline__ void mma_f16(float& c0, float& c1, float& c2, float& c3,
                                        uint32_t a0, uint32_t a1, uint32_t a2, uint32_t a3,
                                        uint32_t b0, uint32_t b1) {
    asm volatile("mma.sync.aligned.m16n8k16.row.col.f32.f16.f16.f32 "
                 "{%0,%1,%2,%3},{%4,%5,%6,%7},{%8,%9},{%0,%1,%2,%3};"
                 : "+f"(c0), "+f"(c1), "+f"(c2), "+f"(c3)
                 : "r"(a0), "r"(a1), "r"(a2), "r"(a3), "r"(b0), "r"(b1));
}
__device__ __forceinline__ void mma_f16_k8(float& c0, float& c1, float& c2, float& c3,
                                           uint32_t a0, uint32_t a1, uint32_t b0) {
    asm volatile("mma.sync.aligned.m16n8k8.row.col.f32.f16.f16.f32 "
                 "{%0,%1,%2,%3},{%4,%5},{%6},{%0,%1,%2,%3};"
                 : "+f"(c0), "+f"(c1), "+f"(c2), "+f"(c3)
                 : "r"(a0), "r"(a1), "r"(b0));
}
#define CPA16(dst_u32, src_ptr) \
    asm volatile("cp.async.cg.shared.global [%0], [%1], 16;" :: "r"(dst_u32), "l"(src_ptr))
#define CP_COMMIT() asm volatile("cp.async.commit_group;")
#define CP_WAIT1()  asm volatile("cp.async.wait_group 1;")
#define CP_WAIT0()  asm volatile("cp.async.wait_group 0;")

// ---------------- K0a: small init (g_acc, g_idx64) ----------------
__global__ void k_init(const int* __restrict__ xraw) {
    int i = threadIdx.x;
    if (i < 8) g_acc[i] = 0.f;
    if (i == 0) {
        int odd = xraw[1] | xraw[3] | xraw[5] | xraw[7] |
                  xraw[9] | xraw[11] | xraw[13] | xraw[15];
        g_idx64 = (odd == 0) ? 1 : 0;
    }
}

// ---------------- K0b: zero g_hT (side stream, before hgemm) ----------------
__global__ void k_zero() {
    int i = blockIdx.x * blockDim.x + threadIdx.x;
    int stride = gridDim.x * blockDim.x;
    for (int j = i; j < BSZ * DIMV; j += stride) g_hT[j] = 0.f;
}

// ---------------- E -> fp16, padded (side stream) ----------------
__global__ void k_ehalf(const float* __restrict__ E) {
    long idx = (long)blockIdx.x * blockDim.x + threadIdx.x;
    if (idx >= (long)NEPAD * 26) return;
    int row = (int)(idx / 26);
    int c8  = (int)(idx % 26) * 8;
    long o  = (long)row * KDPAD + c8;
    if (row < NENT && c8 < DIMV) {
        const float* p = E + (long)row * DIMV + c8;
        #pragma unroll
        for (int j = 0; j < 8; j++) gEh[o + j] = __float2half(p[j]);
    } else {
        #pragma unroll
        for (int j = 0; j < 8; j++) gEh[o + j] = __float2half(0.f);
    }
}

// ---------------- transpose W -> gWTh[e][K] fp16, single pass, fused norm4(W) ----------------
__global__ void k_whalf(const float* __restrict__ W) {
    __shared__ float sT[32][33];
    __shared__ float sr[8];
    int K0 = blockIdx.x * 32;     // 1250 blocks
    int tx = threadIdx.x & 31, ty = threadIdx.x >> 5;
    float p4 = 0.f;
    for (int e0 = 0; e0 < DIMV; e0 += 32) {
        __syncthreads();
        #pragma unroll
        for (int r = 0; r < 4; r++) {
            int Kr = K0 + ty + 8 * r;
            int e  = e0 + tx;
            float v = (e < DIMV) ? W[(long)Kr * DIMV + e] : 0.f;
            sT[ty + 8 * r][tx] = v;
            float a = v * v; p4 += a * a;
        }
        __syncthreads();
        #pragma unroll
        for (int r = 0; r < 4; r++) {
            int ew = e0 + ty + 8 * r;
            if (ew < DIMV)
                gWTh[(long)ew * KBIG + K0 + tx] = __float2half(sT[tx][ty + 8 * r]);
        }
    }
    #pragma unroll
    for (int o = 16; o > 0; o >>= 1) p4 += __shfl_down_sync(0xffffffffu, p4, o);
    if (tx == 0) sr[ty] = p4;
    __syncthreads();
    if (threadIdx.x == 0) {
        float s = 0.f;
        for (int i = 0; i < 8; i++) s += sr[i];
        atomicAdd(&g_acc[4], s);
    }
}

// ---------------- K1: gather v2 — one (b, 8-d-chunk) task per thread ----------------
// Grid 200 x 256 = 51200 threads = 2048 b x 25 chunks. Full utilization, 8-wide
// vectorized loads, x-indices loaded once per task.
__global__ __launch_bounds__(256) void k_gather(const int* __restrict__ x32,
                                                const float* __restrict__ E,
                                                const float* __restrict__ R,
                                                const float* __restrict__ RnoT,
                                                const float* __restrict__ T) {
    __shared__ float sr[3][8];
    int task = blockIdx.x * 256 + threadIdx.x;    // 0..51199
    int b  = task / 25;
    int d0 = (task - b * 25) * 8;
    int x0, x1, x2, x3;
    if (g_idx64) {
        const long long* x64 = (const long long*)x32;
        x0 = (int)x64[(long)b * 4];     x1 = (int)x64[(long)b * 4 + 1];
        x2 = (int)x64[(long)b * 4 + 2]; x3 = (int)x64[(long)b * 4 + 3];
    } else {
        x0 = x32[b * 4]; x1 = x32[b * 4 + 1]; x2 = x32[b * 4 + 2]; x3 = x32[b * 4 + 3];
    }
    float p1 = 0.f, p2 = 0.f, p3 = 0.f;
    #pragma unroll
    for (int g = 0; g < 2; g++) {
        int d = d0 + g * 4;
        float4 lv = *(const float4*)&E[(long)x0 * DIMV + d];
        float4 rv = *(const float4*)&R[x1 * DIMV + d];
        float4 tv = *(const float4*)&T[x3 * DIMV + d];
        float4 rn = *(const float4*)&RnoT[x1 * DIMV + d];
        float4 rh = *(const float4*)&E[(long)x2 * DIMV + d];
        float l[4] = {lv.x, lv.y, lv.z, lv.w};
        float rt[4] = {rv.x * tv.x, rv.y * tv.y, rv.z * tv.z, rv.w * tv.w};
        float n[4] = {rn.x, rn.y, rn.z, rn.w};
        float h[4] = {rh.x, rh.y, rh.z, rh.w};
        #pragma unroll
        for (int j = 0; j < 4; j++) {
            g_lhsT[(d + j) * BSZ + b]  = l[j];
            g_reltT[(d + j) * BSZ + b] = rt[j];
            float a = rt[j] * rt[j]; p1 += a * a;
            float cc = n[j] * n[j];  p2 += cc * cc;
            float e2 = h[j] * h[j];  p3 += e2 * e2;
        }
    }
    #pragma unroll
    for (int o = 16; o > 0; o >>= 1) {
        p1 += __shfl_down_sync(0xffffffffu, p1, o);
        p2 += __shfl_down_sync(0xffffffffu, p2, o);
        p3 += __shfl_down_sync(0xffffffffu, p3, o);
    }
    int lane = threadIdx.x & 31, w = threadIdx.x >> 5;
    if (lane == 0) { sr[0][w] = p1; sr[1][w] = p2; sr[2][w] = p3; }
    __syncthreads();
    if (threadIdx.x == 0) {
        float s1 = 0.f, s2 = 0.f, s3 = 0.f;
        for (int i = 0; i < 8; i++) { s1 += sr[0][i]; s2 += sr[1][i]; s3 += sr[2][i]; }
        atomicAdd(&g_acc[1], s1);
        atomicAdd(&g_acc[2], s2);
        atomicAdd(&g_acc[3], s3);
    }
}

// ---------------- K2: fused BN0 + norm4(lhs_n) ----------------
__global__ __launch_bounds__(256) void k_bn0(const float* __restrict__ gamma,
                                             const float* __restrict__ beta) {
    __shared__ float s1[8], s2[8], sSS[2];
    int d = blockIdx.x, t = threadIdx.x;
    float4 v0 = *(const float4*)&g_lhsT[d * BSZ + t * 8];
    float4 v1 = *(const float4*)&g_lhsT[d * BSZ + t * 8 + 4];
    float vs[8] = {v0.x, v0.y, v0.z, v0.w, v1.x, v1.y, v1.z, v1.w};
    float sum = 0.f, sq = 0.f;
    #pragma unroll
    for (int j = 0; j < 8; j++) { sum += vs[j]; sq += vs[j] * vs[j]; }
    #pragma unroll
    for (int o = 16; o > 0; o >>= 1) {
        sum += __shfl_down_sync(0xffffffffu, sum, o);
        sq  += __shfl_down_sync(0xffffffffu, sq, o);
    }
    int lane = t & 31, w = t >> 5;
    if (lane == 0) { s1[w] = sum; s2[w] = sq; }
    __syncthreads();
    if (t == 0) {
        float S = 0.f, Q = 0.f;
        for (int i = 0; i < 8; i++) { S += s1[i]; Q += s2[i]; }
        float mean = S * (1.f / BSZ);
        float var  = Q * (1.f / BSZ) - mean * mean;
        float inv  = rsqrtf(var + EPSV);
        float sc   = gamma[d] * inv;
        sSS[0] = sc;
        sSS[1] = beta[d] - mean * sc;
    }
    __syncthreads();
    float sc = sSS[0], sh = sSS[1];
    float p4 = 0.f;
    #pragma unroll
    for (int j = 0; j < 8; j++) {
        float nv = vs[j] * sc + sh;
        vs[j] = nv;
        float a = nv * nv; p4 += a * a;
    }
    *(float4*)&g_lhsnT[d * BSZ + t * 8]     = make_float4(vs[0], vs[1], vs[2], vs[3]);
    *(float4*)&g_lhsnT[d * BSZ + t * 8 + 4] = make_float4(vs[4], vs[5], vs[6], vs[7]);
    #pragma unroll
    for (int o = 16; o > 0; o >>= 1) p4 += __shfl_down_sync(0xffffffffu, p4, o);
    if (lane == 0) s1[w] = p4;
    __syncthreads();
    if (t == 0) {
        float s = 0.f;
        for (int i = 0; i < 8; i++) s += s1[i];
        atomicAdd(&g_acc[0], s);
    }
}

// ---------------- K4: h GEMM, fp16 MMA; grid.y=3, wide last tile (N=72) ----------------
__global__ __launch_bounds__(256) void k_hgemm() {
    __shared__ __align__(16) __half sAh[2][128 * KP];
    __shared__ __align__(16) __half sWh[2][WROWS * KP];
    const int t    = threadIdx.x;
    const int lane = t & 31;
    const int w    = t >> 5;
    const int wm   = (w & 1) * 64;
    const int wn   = (w >> 1) * 16;
    const int b0   = blockIdx.x * 128;
    const int e0   = blockIdx.y * 64;
    const int cbeg = blockIdx.z * HSPAN;
    const int nN   = (e0 == 128 && wn == 48) ? 3 : 2;

    const uint32_t uAh = (uint32_t)__cvta_generic_to_shared(sAh);
    const uint32_t uWh = (uint32_t)__cvta_generic_to_shared(sWh);
    const uint32_t bufA = 128 * KP * 2;
    const uint32_t bufW = WROWS * KP * 2;

    const int kk = t & 15;
    const int m4 = t >> 4;

    auto stageW = [&](int buf, int kc) {
        if (t < 2 * WROWS) {
            const __half* src = gWTh + (long)(e0 + (t >> 1)) * KBIG + kc + (t & 1) * 8;
            uint32_t dst = uWh + buf * bufW + (uint32_t)(((t >> 1)) * KP + (t & 1) * 8) * 2;
            CPA16(dst, src);
        }
    };
    auto stageA = [&](int buf, int kc) {
        int K = kc + kk;
        int k = K / DIMV;
        int d = K - k * DIMV;
        const float* rp = &g_reltT[k * BSZ + b0 + m4 * 8];
        const float* lp = &g_lhsnT[d * BSZ + b0 + m4 * 8];
        #pragma unroll
        for (int g = 0; g < 2; g++) {
            float4 rv = *(const float4*)(rp + g * 4);
            float4 lv = *(const float4*)(lp + g * 4);
            float pr[4] = {rv.x * lv.x, rv.y * lv.y, rv.z * lv.z, rv.w * lv.w};
            #pragma unroll
            for (int j = 0; j < 4; j++)
                sAh[buf][(m4 * 8 + g * 4 + j) * KP + kk] = __float2half(pr[j]);
        }
    };

    float c[4][3][4];
    #pragma unroll
    for (int mi = 0; mi < 4; mi++)
        #pragma unroll
        for (int ni = 0; ni < 3; ni++)
            #pragma unroll
            for (int q = 0; q < 4; q++) c[mi][ni][q] = 0.f;

    stageW(0, cbeg * 16);
    CP_COMMIT();
    stageA(0, cbeg * 16);

    for (int cI = 0; cI < HSPAN; cI++) {
        int buf = cI & 1;
        if (cI + 1 < HSPAN) {
            stageW(buf ^ 1, (cbeg + cI + 1) * 16);
            CP_COMMIT();
            stageA(buf ^ 1, (cbeg + cI + 1) * 16);
        } else {
            CP_COMMIT();
        }
        CP_WAIT1();
        __syncthreads();

        uint32_t aAh = uAh + buf * bufA;
        uint32_t aWh = uWh + buf * bufW;
        uint32_t ah[4][4];
        {
            int arow = wm + (lane & 15);
            int acol = (lane >> 4) * 8;
            #pragma unroll
            for (int mi = 0; mi < 4; mi++) {
                uint32_t off = (uint32_t)(((arow + mi * 16) * KP + acol) * 2);
                ldsm_x4(ah[mi][0], ah[mi][1], ah[mi][2], ah[mi][3], aAh + off);
            }
        }
        uint32_t bh[4], bx[4];
        {
            int r = lane & 7, seg = lane >> 3;
            int brow = wn + ((seg & 2) ? 8 : 0) + r;
            int bcol = (seg & 1) * 8;
            uint32_t off = (uint32_t)((brow * KP + bcol) * 2);
            ldsm_x4(bh[0], bh[1], bh[2], bh[3], aWh + off);
            if (nN == 3) {
                uint32_t off2 = (uint32_t)(((brow + 16) * KP + bcol) * 2);
                ldsm_x4(bx[0], bx[1], bx[2], bx[3], aWh + off2);
            }
        }
        #pragma unroll
        for (int mi = 0; mi < 4; mi++) {
            float* c0 = c[mi][0];
            mma_f16(c0[0], c0[1], c0[2], c0[3],
                    ah[mi][0], ah[mi][1], ah[mi][2], ah[mi][3], bh[0], bh[1]);
            float* c1 = c[mi][1];
            mma_f16(c1[0], c1[1], c1[2], c1[3],
                    ah[mi][0], ah[mi][1], ah[mi][2], ah[mi][3], bh[2], bh[3]);
            if (nN == 3) {
                float* c2 = c[mi][2];
                mma_f16(c2[0], c2[1], c2[2], c2[3],
                        ah[mi][0], ah[mi][1], ah[mi][2], ah[mi][3], bx[0], bx[1]);
            }
        }
        __syncthreads();
    }

    #pragma unroll
    for (int mi = 0; mi < 4; mi++) {
        for (int ni = 0; ni < nN; ni++) {
            int r  = b0 + wm + mi * 16 + (lane >> 2);
            int cg = e0 + wn + ni * 8 + (lane & 3) * 2;
            if (cg < DIMV) {
                float* cc = c[mi][ni];
                atomicAdd(&g_hT[cg * BSZ + r], cc[0]);
                atomicAdd(&g_hT[(cg + 1) * BSZ + r], cc[1]);
                atomicAdd(&g_hT[cg * BSZ + r + 8], cc[2]);
                atomicAdd(&g_hT[(cg + 1) * BSZ + r + 8], cc[3]);
            }
        }
    }
}

// ---------------- K5: fused BN1 -> gAh fp16 [b][200] ----------------
__global__ __launch_bounds__(256) void k_bn1(const float* __restrict__ gamma,
                                             const float* __restrict__ beta) {
    __shared__ float s1[8], s2[8], sSS[2];
    int e = blockIdx.x, t = threadIdx.x;
    float4 v0 = *(const float4*)&g_hT[e * BSZ + t * 8];
    float4 v1 = *(const float4*)&g_hT[e * BSZ + t * 8 + 4];
    float vs[8] = {v0.x, v0.y, v0.z, v0.w, v1.x, v1.y, v1.z, v1.w};
    float sum = 0.f, sq = 0.f;
    #pragma unroll
    for (int j = 0; j < 8; j++) { sum += vs[j]; sq += vs[j] * vs[j]; }
    #pragma unroll
    for (int o = 16; o > 0; o >>= 1) {
        sum += __shfl_down_sync(0xffffffffu, sum, o);
        sq  += __shfl_down_sync(0xffffffffu, sq, o);
    }
    int lane = t & 31, w = t >> 5;
    if (lane == 0) { s1[w] = sum; s2[w] = sq; }
    __syncthreads();
    if (t == 0) {
        float S = 0.f, Q = 0.f;
        for (int i = 0; i < 8; i++) { S += s1[i]; Q += s2[i]; }
        float mean = S * (1.f / BSZ);
        float var  = Q * (1.f / BSZ) - mean * mean;
        float inv  = rsqrtf(var + EPSV);
        float sc   = gamma[e] * inv;
        sSS[0] = sc;
        sSS[1] = beta[e] - mean * sc;
    }
    __syncthreads();
    float sc = sSS[0], sh = sSS[1];
    #pragma unroll
    for (int j = 0; j < 8; j++)
        gAh[(t * 8 + j) * DIMV + e] = __float2half(vs[j] * sc + sh);
}

// ---------------- K7: pred = h_n @ E^T; 3-buffer A ring, 1 sync/iter ----------------
__global__ __launch_bounds__(256) void k_pred(float* __restrict__ out) {
    extern __shared__ __align__(16) char dynsmem[];
    __half* sE = (__half*)dynsmem;                       // 128 x EP
    __half* sA = (__half*)(dynsmem + 128 * EP * 2);      // 3 x 128 x KP
    const int t    = threadIdx.x;
    const int lane = t & 31;
    const int w    = t >> 5;
    const int wm   = (w & 1) * 64;
    const int wn   = (w >> 1) * 32;
    const int et   = blockIdx.x / 3;
    const int grp  = blockIdx.x - et * 3;
    const int e0   = et * 128;
    const int mbeg = (grp == 0) ? 0 : (grp == 1 ? 6 : 11);
    const int mend = (grp == 0) ? 6 : (grp == 1 ? 11 : 16);
    const int nit  = (mend - mbeg) * 13;

    const uint32_t uE = (uint32_t)__cvta_generic_to_shared(sE);
    const uint32_t uA = (uint32_t)__cvta_generic_to_shared(sA);
    const uint32_t bufA = 128 * KP * 2;

    const int srow = t >> 1;
    const int sch  = (t & 1) * 8;
    auto stageA = [&](int buf, int mIdx, int kcIdx) {
        if (kcIdx < 12 || (t & 1) == 0)
            CPA16(uA + buf * bufA + (uint32_t)(srow * KP + sch) * 2,
                  gAh + (long)(mIdx * 128 + srow) * DIMV + kcIdx * 16 + sch);
    };

    for (int i = t; i < 128 * 26; i += 256) {
        int row = i / 26, c = i - row * 26;
        CPA16(uE + (uint32_t)(row * EP + c * 8) * 2,
              gEh + (long)(e0 + row) * KDPAD + c * 8);
    }
    stageA(0, mbeg, 0);
    CP_COMMIT();
    stageA(1, mbeg, 1);
    CP_COMMIT();

    float c[4][4][4];
    #pragma unroll
    for (int mi = 0; mi < 4; mi++)
        #pragma unroll
        for (int ni = 0; ni < 4; ni++)
            #pragma unroll
            for (int q = 0; q < 4; q++) c[mi][ni][q] = 0.f;

    int m = mbeg, kc = 0;
    for (int it = 0; it < nit; it++) {
        CP_WAIT1();
        __syncthreads();

        if (it + 2 < nit) {
            int k2 = kc + 2, m2 = m;
            if (k2 >= 13) { k2 -= 13; m2++; }
            stageA((it + 2) % 3, m2, k2);
        }
        CP_COMMIT();

        uint32_t aA = uA + (it % 3) * bufA;
        uint32_t ah[4][4];
        {
            int arow = wm + (lane & 15);
            int acol = (lane >> 4) * 8;
            #pragma unroll
            for (int mi = 0; mi < 4; mi++) {
                uint32_t off = (uint32_t)(((arow + mi * 16) * KP + acol) * 2);
                ldsm_x4(ah[mi][0], ah[mi][1], ah[mi][2], ah[mi][3], aA + off);
            }
        }
        uint32_t bh[2][4];
        {
            int r = lane & 7, seg = lane >> 3;
            int brow_in = ((seg & 2) ? 8 : 0) + r;
            int bcol = (seg & 1) * 8;
            #pragma unroll
            for (int p = 0; p < 2; p++) {
                uint32_t off = (uint32_t)(((wn + p * 16 + brow_in) * EP + kc * 16 + bcol) * 2);
                ldsm_x4(bh[p][0], bh[p][1], bh[p][2], bh[p][3], uE + off);
            }
        }
        if (kc < 12) {
            #pragma unroll
            for (int mi = 0; mi < 4; mi++) {
                #pragma unroll
                for (int ni = 0; ni < 4; ni++) {
                    int p = ni >> 1, q = (ni & 1) * 2;
                    float* cc = c[mi][ni];
                    mma_f16(cc[0], cc[1], cc[2], cc[3],
                            ah[mi][0], ah[mi][1], ah[mi][2], ah[mi][3], bh[p][q], bh[p][q + 1]);
                }
            }
        } else {
            #pragma unroll
            for (int mi = 0; mi < 4; mi++) {
                #pragma unroll
                for (int ni = 0; ni < 4; ni++) {
                    int p = ni >> 1, q = (ni & 1) * 2;
                    float* cc = c[mi][ni];
                    mma_f16_k8(cc[0], cc[1], cc[2], cc[3],
                               ah[mi][0], ah[mi][1], bh[p][q]);
                }
            }
        }

        if (kc == 12) {
            #pragma unroll
            for (int mi = 0; mi < 4; mi++) {
                #pragma unroll
                for (int ni = 0; ni < 4; ni++) {
                    int r  = m * 128 + wm + mi * 16 + (lane >> 2);
                    int cg = e0 + wn + ni * 8 + (lane & 3) * 2;
                    float* cc = c[mi][ni];
                    if (cg < NENT) {
                        *(float2*)&out[(long)r * NENT + cg]       = make_float2(cc[0], cc[1]);
                        *(float2*)&out[(long)(r + 8) * NENT + cg] = make_float2(cc[2], cc[3]);
                    }
                    cc[0] = cc[1] = cc[2] = cc[3] = 0.f;
                }
            }
            kc = 0; m++;
        } else {
            kc++;
        }
    }
}

// ---------------- K9: reg outputs + T passthrough (side stream) ----------------
__global__ void k_tail(const float* __restrict__ T, float* __restrict__ out) {
    int i = blockIdx.x * blockDim.x + threadIdx.x;
    if (i < 5) out[REG_OFF + i] = powf(g_acc[i], 0.25f);
    if (i < NTS * DIMV) out[T_OFF + i] = T[i];
}

// ---------------- launch ----------------
extern "C" void kernel_launch(void* const* d_in, const int* in_sizes, int n_in,
                              void* d_out, int out_size) {
    const int*   x    = (const int*)d_in[0];
    const float* E    = (const float*)d_in[1];
    const float* R    = (const float*)d_in[2];
    const float* RnoT = (const float*)d_in[3];
    const float* T    = (const float*)d_in[4];
    const float* W    = (const float*)d_in[5];
    const float* g0   = (const float*)d_in[6];
    const float* be0  = (const float*)d_in[7];
    const float* g1   = (const float*)d_in[8];
    const float* be1  = (const float*)d_in[9];
    float* out = (float*)d_out;

    static cudaStream_t s2 = 0;
    static cudaEvent_t evF = 0, evW = 0, evE = 0, evB = 0, evT = 0;
    if (s2 == 0) {
        cudaStreamCreateWithFlags(&s2, cudaStreamNonBlocking);
        cudaEventCreateWithFlags(&evF, cudaEventDisableTiming);
        cudaEventCreateWithFlags(&evW, cudaEventDisableTiming);
        cudaEventCreateWithFlags(&evE, cudaEventDisableTiming);
        cudaEventCreateWithFlags(&evB, cudaEventDisableTiming);
        cudaEventCreateWithFlags(&evT, cudaEventDisableTiming);
    }
    cudaFuncSetAttribute(k_pred, cudaFuncAttributeMaxDynamicSharedMemorySize, PRED_SMEM);

    k_init<<<1, 256>>>(x);
    cudaEventRecord(evF, 0);
    cudaStreamWaitEvent(s2, evF, 0);
    k_zero<<<512, 256, 0, s2>>>();
    k_whalf<<<1250, 256, 0, s2>>>(W);
    cudaEventRecord(evW, s2);
    k_ehalf<<<(int)(((long)NEPAD * 26 + 255) / 256), 256, 0, s2>>>(E);
    cudaEventRecord(evE, s2);

    k_gather<<<200, 256>>>(x, E, R, RnoT, T);
    k_bn0<<<DIMV, 256>>>(g0, be0);
    cudaEventRecord(evB, 0);
    cudaStreamWaitEvent(0, evW, 0);
    k_hgemm<<<dim3(16, 3, HZ), 256>>>();
    k_bn1<<<DIMV, 256>>>(g1, be1);

    cudaStreamWaitEvent(s2, evB, 0);
    k_tail<<<320, 256, 0, s2>>>(T, out);
    cudaEventRecord(evT, s2);

    cudaStreamWaitEvent(0, evE, 0);
    k_pred<<<2346, 256, PRED_SMEM>>>(out);
    cudaStreamWaitEvent(0, evT, 0);
}